// round 4
// baseline (speedup 1.0000x reference)
#include <cuda_runtime.h>

#define N_PRIORS    400000
#define N4          100000
#define N_CLASSES   81
#define K_CAND      1000
#define CAP         2048
#define IOU_THR     0.5f
#define SCORE_THR   0.3f
#define MID_BLOCKS  128
#define MID_THREADS 512
#define ELEMS       (MID_BLOCKS * MID_THREADS)   // 65536 threads; 2 uint4 each

// ---------------- scratch (static device globals; no allocation) ----------------
__device__ __align__(16) unsigned g_keys[N_PRIORS];  // float bits of best score
__device__ unsigned char       g_labels[N_PRIORS];   // argmax over classes 1..80 (0..79)
__device__ unsigned long long  g_cand[CAP];          // (key<<32) | (0xFFFFFFFF - prior_idx)
__device__ unsigned            g_sup[K_CAND * 32];   // suppression bitmask rows (j>i only)
__device__ float g_cx1[1024], g_cy1[1024], g_cx2[1024], g_cy2[1024], g_cscore[1024];
__device__ int   g_clabel[1024];
__device__ unsigned g_hist[4][256];
__device__ unsigned g_count;
__device__ unsigned g_syncctr[8];

// ---------------- software grid barrier (all MID_BLOCKS co-resident) ----------------
__device__ __forceinline__ void grid_sync(int id) {
  __syncthreads();
  if (threadIdx.x == 0) {
    __threadfence();
    volatile unsigned* c = &g_syncctr[id];
    atomicAdd((unsigned*)c, 1u);
    while (*c < (unsigned)MID_BLOCKS) __nanosleep(20);
  }
  __syncthreads();
}

// ---------------- per-prior max/argmax over classes 1..80 (warp per prior) ----------------
// Block 0 also zeroes all interphase state (consumed only by later kernels).
__global__ void k_reduce(const float* __restrict__ scores) {
  if (blockIdx.x == 0) {
    int t = threadIdx.x;
    for (int i = t; i < 4 * 256; i += blockDim.x) (&g_hist[0][0])[i] = 0u;
    if (t < 8) g_syncctr[t] = 0u;
    if (t == 0) g_count = 0u;
  }
  int lane  = threadIdx.x & 31;
  int warp  = (blockIdx.x * blockDim.x + threadIdx.x) >> 5;
  int nwarp = (gridDim.x * blockDim.x) >> 5;
  for (int p = warp; p < N_PRIORS; p += nwarp) {
    const float* row = scores + (size_t)p * N_CLASSES;
    // streaming loads; float bits are order-preserving for scores >= 0
    unsigned u0 = __float_as_uint(__ldcs(row + 1 + lane));                         // cls lane
    unsigned u1 = __float_as_uint(__ldcs(row + 33 + lane));                        // cls 32+lane
    unsigned u2 = (lane < 16) ? __float_as_uint(__ldcs(row + 65 + lane)) : 0u;     // cls 64+lane
    unsigned loc = u0 > u1 ? u0 : u1;
    if (u2 > loc) loc = u2;
    unsigned m = __reduce_max_sync(0xFFFFFFFFu, loc);
    // first (lowest) class index achieving max — matches argmax semantics
    unsigned b0 = __ballot_sync(0xFFFFFFFFu, u0 == m);
    unsigned b1 = __ballot_sync(0xFFFFFFFFu, u1 == m);
    unsigned b2 = __ballot_sync(0xFFFFFFFFu, (lane < 16) && (u2 == m));
    if (lane == 0) {
      int idx = b0 ? (__ffs(b0) - 1) : (b1 ? (31 + __ffs(b1)) : (63 + __ffs(b2)));
      g_keys[p]   = m;
      g_labels[p] = (unsigned char)idx;
    }
  }
}

// ---------------- fused: 4x radix-select + compact + sort + IoU matrix ----------------
__global__ __launch_bounds__(MID_THREADS) void k_mid(const float* __restrict__ boxes) {
  __shared__ unsigned h[256];
  __shared__ unsigned s_prefix;
  __shared__ unsigned long long s_sort[CAP];                        // 16 KB (block 0)
  __shared__ float sx1[K_CAND], sy1[K_CAND], sx2[K_CAND], sy2[K_CAND], sar[K_CAND];

  int tid  = threadIdx.x;
  int lane = tid & 31;
  int gt   = blockIdx.x * MID_THREADS + tid;

  // ---- load this thread's 8 keys into registers (read g_keys exactly once) ----
  uint4 k0 = make_uint4(0, 0, 0, 0), k1 = make_uint4(0, 0, 0, 0);
  bool in0 = gt < N4;
  bool in1 = (gt + ELEMS) < N4;
  if (in0) k0 = ((const uint4*)g_keys)[gt];
  if (in1) k1 = ((const uint4*)g_keys)[gt + ELEMS];

  unsigned prefix = 0;
  unsigned kk = K_CAND;   // rank remaining; meaningful on tid==0 only

#pragma unroll
  for (int R = 0; R < 4; R++) {
    const int SHIFT = 24 - 8 * R;
    if (tid < 256) h[tid] = 0u;
    __syncthreads();
#pragma unroll
    for (int e = 0; e < 8; e++) {
      unsigned key = (e < 4) ? (&k0.x)[e] : (&k1.x)[e - 4];
      bool valid   = (e < 4) ? in0 : in1;
      unsigned hi  = (R == 0) ? 0u : (key >> ((SHIFT + 8) & 31));
      bool match   = valid && (R == 0 || hi == prefix);
      unsigned bin = match ? ((key >> SHIFT) & 255u) : 0xFFFFFFFFu;
      unsigned peers = __match_any_sync(0xFFFFFFFFu, bin);
      if (bin != 0xFFFFFFFFu && lane == (__ffs(peers) - 1))
        atomicAdd(&h[bin], (unsigned)__popc(peers));
    }
    __syncthreads();
    if (tid < 256 && h[tid]) atomicAdd(&g_hist[R][tid], h[tid]);
    grid_sync(R);
    // redundant per-block scan of the completed global histogram
    if (tid < 256) h[tid] = __ldcg(&g_hist[R][tid]);
    __syncthreads();
    if (tid == 0) {
      unsigned k = kk;
      int b = 255;
      for (; b > 0; b--) {
        unsigned c = h[b];
        if (k <= c) break;
        k -= c;
      }
      kk = k;
      s_prefix = (prefix << 8) | (unsigned)b;
    }
    __syncthreads();
    prefix = s_prefix;
  }
  unsigned kth = prefix;   // full 32-bit kth key after 4 rounds

  // ---- compact candidates with key >= kth ----
#pragma unroll
  for (int e = 0; e < 8; e++) {
    unsigned key = (e < 4) ? (&k0.x)[e] : (&k1.x)[e - 4];
    bool valid   = (e < 4) ? in0 : in1;
    unsigned idx = (e < 4) ? (unsigned)(4 * gt + e)
                           : (unsigned)(4 * (gt + ELEMS) + (e - 4));
    if (valid && key >= kth) {
      unsigned pos = atomicAdd(&g_count, 1u);
      if (pos < CAP)
        g_cand[pos] = ((unsigned long long)key << 32) | (unsigned long long)(0xFFFFFFFFu - idx);
    }
  }
  grid_sync(4);

  // ---- block 0: bitonic sort (2048) + gather candidate SoA ----
  if (blockIdx.x == 0) {
    unsigned n = __ldcg(&g_count);
    if (n > CAP) n = CAP;
    for (int t = tid; t < CAP; t += MID_THREADS)
      s_sort[t] = (t < (int)n) ? __ldcg(&g_cand[t]) : 0ull;
    __syncthreads();
    for (int k = 2; k <= CAP; k <<= 1) {
      for (int j = k >> 1; j > 0; j >>= 1) {
        for (int idx = tid; idx < CAP; idx += MID_THREADS) {
          int l = idx ^ j;
          if (l > idx) {
            unsigned long long a = s_sort[idx], b = s_sort[l];
            bool up = ((idx & k) == 0);
            if ((a > b) == up) { s_sort[idx] = b; s_sort[l] = a; }
          }
        }
        __syncthreads();
      }
    }
    for (int t = tid; t < K_CAND; t += MID_THREADS) {
      unsigned long long e = s_sort[CAP - 1 - t];   // rank t descending
      unsigned key = (unsigned)(e >> 32);
      unsigned idx = 0xFFFFFFFFu - (unsigned)e;
      float4 bb = ((const float4*)boxes)[idx];
      g_cx1[t] = bb.x; g_cy1[t] = bb.y; g_cx2[t] = bb.z; g_cy2[t] = bb.w;
      g_cscore[t] = __uint_as_float(key);
      g_clabel[t] = (int)g_labels[idx];
    }
  }
  grid_sync(5);

  // ---- all blocks: suppression bitmask matrix (offset boxes, j > i) ----
  for (int t = tid; t < K_CAND; t += MID_THREADS) {
    float off = (float)__ldcg(&g_clabel[t]) * 4.0f;
    float x1 = __ldcg(&g_cx1[t]) + off, y1 = __ldcg(&g_cy1[t]) + off;
    float x2 = __ldcg(&g_cx2[t]) + off, y2 = __ldcg(&g_cy2[t]) + off;
    sx1[t] = x1; sy1[t] = y1; sx2[t] = x2; sy2[t] = y2;
    sar[t] = (x2 - x1) * (y2 - y1);   // area from offset coords, like reference
  }
  __syncthreads();
  if (gt < K_CAND * 32) {
    int i = gt >> 5;
    int w = gt & 31;
    float x1 = sx1[i], y1 = sy1[i], x2 = sx2[i], y2 = sy2[i], ai = sar[i];
    unsigned word = 0u;
#pragma unroll
    for (int jj = 0; jj < 32; jj++) {
      int j = w * 32 + jj;
      if (j > i && j < K_CAND) {
        float xx1 = fmaxf(x1, sx1[j]);
        float yy1 = fmaxf(y1, sy1[j]);
        float xx2 = fminf(x2, sx2[j]);
        float yy2 = fminf(y2, sy2[j]);
        float inter = fmaxf(xx2 - xx1, 0.0f) * fmaxf(yy2 - yy1, 0.0f);
        float uni = fmaxf(ai + sar[j] - inter, 1e-9f);
        float iou = __fdiv_rn(inter, uni);
        if (iou > IOU_THR) word |= (1u << jj);
      }
    }
    g_sup[i * 32 + w] = word;
  }
}

// ---------------- final: sequential greedy reduction (1 warp) + output write ----------------
__global__ void k_final(float* __restrict__ out) {
  extern __shared__ unsigned ssup[];  // 32000 words = 128000 B
  __shared__ unsigned skeep[32];
  for (int t = threadIdx.x; t < K_CAND * 32; t += blockDim.x)
    ssup[t] = g_sup[t];
  __syncthreads();

  if (threadIdx.x < 32) {
    int lane = threadIdx.x;
    unsigned kw = 0u;  // keep word for columns [32*lane, 32*lane+32)
#pragma unroll
    for (int jj = 0; jj < 32; jj++) {
      int j = lane * 32 + jj;
      bool v = (j < K_CAND) && (g_cscore[j] > SCORE_THR);
      if (v) kw |= (1u << jj);
    }
    for (int c = 0; c < 32; c++) {
      unsigned bkw = __shfl_sync(0xFFFFFFFFu, kw, c);  // current chunk's keep word
      int base = c * 32;
#pragma unroll
      for (int r = 0; r < 32; r++) {
        int i = base + r;
        if (i < K_CAND) {
          unsigned rowl = ssup[i * 32 + lane];  // conflict-free
          unsigned rowc = ssup[i * 32 + c];     // broadcast
          if (bkw & (1u << r)) {
            kw  &= ~rowl;
            bkw &= ~rowc;
          }
        }
      }
    }
    skeep[lane] = kw;
  }
  __syncthreads();

  int t = threadIdx.x;
  if (t < K_CAND) {
    bool keep = (skeep[t >> 5] >> (t & 31)) & 1u;
    float kf = keep ? 1.0f : 0.0f;
    out[t * 4 + 0] = g_cx1[t] * kf;
    out[t * 4 + 1] = g_cy1[t] * kf;
    out[t * 4 + 2] = g_cx2[t] * kf;
    out[t * 4 + 3] = g_cy2[t] * kf;
    out[4000 + t] = keep ? (float)(g_clabel[t] + 1) : 0.0f;
    out[5000 + t] = g_cscore[t] * kf;
    out[6000 + t] = kf;
  }
}

// ---------------- launch ----------------
extern "C" void kernel_launch(void* const* d_in, const int* in_sizes, int n_in,
                              void* d_out, int out_size) {
  const float* scores = (const float*)d_in[0];
  const float* boxes  = (const float*)d_in[1];
  float* out = (float*)d_out;

  cudaFuncSetAttribute(k_final, cudaFuncAttributeMaxDynamicSharedMemorySize, 128000);

  k_reduce<<<1184, 256>>>(scores);          // 148 SMs x 8 blocks = 1 full wave
  k_mid<<<MID_BLOCKS, MID_THREADS>>>(boxes);
  k_final<<<1, 1024, 128000>>>(out);
}

// round 6
// speedup vs baseline: 1.0837x; 1.0837x over previous
#include <cuda_runtime.h>

#define N_PRIORS    400000
#define N4          100000
#define N_CLASSES   81
#define K_CAND      1000
#define CAP         2048
#define IOU_THR     0.5f
#define SCORE_THR   0.3f
#define MID_BLOCKS  128
#define MID_THREADS 512
#define ELEMS       (MID_BLOCKS * MID_THREADS)   // 65536 threads; 8 keys each

// ---------------- scratch (static device globals; no allocation) ----------------
__device__ __align__(16) unsigned g_keys[N_PRIORS];  // float bits of best score
__device__ unsigned char       g_labels[N_PRIORS];   // argmax over classes 1..80 (0..79)
__device__ unsigned long long  g_cand[CAP];          // (key<<32) | (0xFFFFFFFF - prior_idx)
__device__ unsigned            g_sup[K_CAND * 32];   // suppression bitmask rows (j>i only)
__device__ float g_cx1[1024], g_cy1[1024], g_cx2[1024], g_cy2[1024], g_cscore[1024];
__device__ int   g_clabel[1024];
__device__ unsigned g_hist[4][256];
__device__ unsigned g_count;
__device__ unsigned g_syncctr[8];

// ---------------- software grid barrier (all MID_BLOCKS co-resident) ----------------
__device__ __forceinline__ void grid_sync(int id) {
  __threadfence();       // every thread orders its own global stores first
  __syncthreads();
  if (threadIdx.x == 0) {
    volatile unsigned* c = &g_syncctr[id];
    atomicAdd((unsigned*)c, 1u);
    while (*c < (unsigned)MID_BLOCKS) __nanosleep(20);
  }
  __syncthreads();
}

// ---------------- per-prior max/argmax over classes 1..80 (warp per 2 priors) ----------------
// Block 0 also zeroes all interphase state (consumed only by later kernels).
__global__ void k_reduce(const float* __restrict__ scores) {
  if (blockIdx.x == 0) {
    int t = threadIdx.x;
    for (int i = t; i < 4 * 256; i += blockDim.x) (&g_hist[0][0])[i] = 0u;
    if (t < 8) g_syncctr[t] = 0u;
    if (t == 0) g_count = 0u;
  }
  int lane  = threadIdx.x & 31;
  int warp  = (blockIdx.x * blockDim.x + threadIdx.x) >> 5;
  int nwarp = (gridDim.x * blockDim.x) >> 5;
  for (int p = warp * 2; p < N_PRIORS; p += nwarp * 2) {
    const float* rowA = scores + (size_t)p * N_CLASSES;
    const float* rowB = rowA + N_CLASSES;
    // 6 independent streaming loads up front (bits order-preserving for >= 0)
    unsigned a0 = __float_as_uint(__ldcs(rowA + 1 + lane));
    unsigned a1 = __float_as_uint(__ldcs(rowA + 33 + lane));
    unsigned a2 = (lane < 16) ? __float_as_uint(__ldcs(rowA + 65 + lane)) : 0u;
    unsigned b0 = __float_as_uint(__ldcs(rowB + 1 + lane));
    unsigned b1 = __float_as_uint(__ldcs(rowB + 33 + lane));
    unsigned b2 = (lane < 16) ? __float_as_uint(__ldcs(rowB + 65 + lane)) : 0u;

    unsigned locA = a0 > a1 ? a0 : a1; if (a2 > locA) locA = a2;
    unsigned locB = b0 > b1 ? b0 : b1; if (b2 > locB) locB = b2;
    unsigned mA = __reduce_max_sync(0xFFFFFFFFu, locA);
    unsigned mB = __reduce_max_sync(0xFFFFFFFFu, locB);
    // lowest class index achieving the max (argmax semantics)
    unsigned cA = (a0 == mA) ? (unsigned)lane
                : (a1 == mA) ? (unsigned)(32 + lane)
                : ((lane < 16) && (a2 == mA)) ? (unsigned)(64 + lane) : 255u;
    unsigned cB = (b0 == mB) ? (unsigned)lane
                : (b1 == mB) ? (unsigned)(32 + lane)
                : ((lane < 16) && (b2 == mB)) ? (unsigned)(64 + lane) : 255u;
    unsigned iA = __reduce_min_sync(0xFFFFFFFFu, cA);
    unsigned iB = __reduce_min_sync(0xFFFFFFFFu, cB);
    if (lane == 0) {
      g_keys[p]       = mA;
      g_keys[p + 1]   = mB;
      g_labels[p]     = (unsigned char)iA;
      g_labels[p + 1] = (unsigned char)iB;
    }
  }
}

// ---------------- fused: 4x radix-select + compact + rank-scatter + IoU matrix ----------------
__global__ __launch_bounds__(MID_THREADS) void k_mid(const float* __restrict__ boxes) {
  __shared__ unsigned h[256];
  __shared__ unsigned s_prefix;
  __shared__ unsigned long long s_cand[CAP];                        // 16 KB
  __shared__ float sx1[K_CAND], sy1[K_CAND], sx2[K_CAND], sy2[K_CAND], sar[K_CAND];

  int tid  = threadIdx.x;
  int lane = tid & 31;
  int gt   = blockIdx.x * MID_THREADS + tid;

  // ---- load this thread's 8 keys into registers (read g_keys exactly once) ----
  // gt < 65536 < N4 always; second slab guarded.
  uint4 k0 = ((const uint4*)g_keys)[gt];
  uint4 k1 = make_uint4(0, 0, 0, 0);
  bool in1 = (gt + ELEMS) < N4;
  if (in1) k1 = ((const uint4*)g_keys)[gt + ELEMS];

  unsigned prefix = 0;
  unsigned kk = K_CAND;   // rank remaining; meaningful on tid==0 only

#pragma unroll
  for (int R = 0; R < 4; R++) {
    const int SHIFT = 24 - 8 * R;
    if (tid < 256) h[tid] = 0u;
    __syncthreads();
#pragma unroll
    for (int e = 0; e < 8; e++) {
      unsigned key = (e < 4) ? (&k0.x)[e] : (&k1.x)[e - 4];
      bool valid   = (e < 4) ? true : in1;
      unsigned hi  = (R == 0) ? 0u : (key >> ((SHIFT + 8) & 31));
      bool match   = valid && (R == 0 || hi == prefix);
      unsigned bin = match ? ((key >> SHIFT) & 255u) : 0xFFFFFFFFu;
      unsigned peers = __match_any_sync(0xFFFFFFFFu, bin);
      if (bin != 0xFFFFFFFFu && lane == (__ffs(peers) - 1))
        atomicAdd(&h[bin], (unsigned)__popc(peers));
    }
    __syncthreads();
    if (tid < 256 && h[tid]) atomicAdd(&g_hist[R][tid], h[tid]);
    grid_sync(R);
    // redundant per-block scan of the completed global histogram
    if (tid < 256) h[tid] = __ldcg(&g_hist[R][tid]);
    __syncthreads();
    if (tid == 0) {
      unsigned k = kk;
      int b = 255;
      for (; b > 0; b--) {
        unsigned c = h[b];
        if (k <= c) break;
        k -= c;
      }
      kk = k;
      s_prefix = (prefix << 8) | (unsigned)b;
    }
    __syncthreads();
    prefix = s_prefix;
  }
  unsigned kth = prefix;   // full 32-bit kth key after 4 rounds

  // ---- compact candidates with key >= kth ----
#pragma unroll
  for (int e = 0; e < 8; e++) {
    unsigned key = (e < 4) ? (&k0.x)[e] : (&k1.x)[e - 4];
    bool valid   = (e < 4) ? true : in1;
    unsigned idx = (e < 4) ? (unsigned)(4 * gt + e)
                           : (unsigned)(4 * (gt + ELEMS) + (e - 4));
    if (valid && key >= kth) {
      unsigned pos = atomicAdd(&g_count, 1u);
      if (pos < CAP)
        g_cand[pos] = ((unsigned long long)key << 32) | (unsigned long long)(0xFFFFFFFFu - idx);
    }
  }
  grid_sync(4);

  // ---- parallel rank-selection: candidate's rank = #{larger candidates} ----
  {
    unsigned n = __ldcg(&g_count);
    if (n > CAP) n = CAP;
    for (int t = tid; t < (int)n; t += MID_THREADS)
      s_cand[t] = __ldcg(&g_cand[t]);
    __syncthreads();
    if (gt < (int)n) {
      unsigned long long e = s_cand[gt];
      int r = 0;
      for (int j = 0; j < (int)n; j++)
        r += (s_cand[j] > e);               // 64-bit keys are unique (idx packed)
      unsigned key = (unsigned)(e >> 32);
      unsigned idx = 0xFFFFFFFFu - (unsigned)e;
      if (r < K_CAND && idx < (unsigned)N_PRIORS) {   // guard: degrade, don't fault
        float4 bb = ((const float4*)boxes)[idx];
        g_cx1[r] = bb.x; g_cy1[r] = bb.y; g_cx2[r] = bb.z; g_cy2[r] = bb.w;
        g_cscore[r] = __uint_as_float(key);
        g_clabel[r] = (int)g_labels[idx];
      }
    }
  }
  grid_sync(5);

  // ---- all blocks: suppression bitmask matrix (offset boxes, j > i) ----
  for (int t = tid; t < K_CAND; t += MID_THREADS) {
    float off = (float)__ldcg(&g_clabel[t]) * 4.0f;
    float x1 = __ldcg(&g_cx1[t]) + off, y1 = __ldcg(&g_cy1[t]) + off;
    float x2 = __ldcg(&g_cx2[t]) + off, y2 = __ldcg(&g_cy2[t]) + off;
    sx1[t] = x1; sy1[t] = y1; sx2[t] = x2; sy2[t] = y2;
    sar[t] = (x2 - x1) * (y2 - y1);   // area from offset coords, like reference
  }
  __syncthreads();
  if (gt < K_CAND * 32) {
    int i = gt >> 5;
    int w = gt & 31;
    float x1 = sx1[i], y1 = sy1[i], x2 = sx2[i], y2 = sy2[i], ai = sar[i];
    unsigned word = 0u;
#pragma unroll
    for (int jj = 0; jj < 32; jj++) {
      int j = w * 32 + jj;
      if (j > i && j < K_CAND) {
        float xx1 = fmaxf(x1, sx1[j]);
        float yy1 = fmaxf(y1, sy1[j]);
        float xx2 = fminf(x2, sx2[j]);
        float yy2 = fminf(y2, sy2[j]);
        float inter = fmaxf(xx2 - xx1, 0.0f) * fmaxf(yy2 - yy1, 0.0f);
        float uni = fmaxf(ai + sar[j] - inter, 1e-9f);
        float iou = __fdiv_rn(inter, uni);
        if (iou > IOU_THR) word |= (1u << jj);
      }
    }
    g_sup[i * 32 + w] = word;
  }
}

// ---------------- final: sequential greedy reduction (1 warp) + output write ----------------
__global__ void k_final(float* __restrict__ out) {
  extern __shared__ unsigned ssup[];  // 32000 words = 128000 B
  __shared__ unsigned skeep[32];
  for (int t = threadIdx.x; t < K_CAND * 32; t += blockDim.x)
    ssup[t] = g_sup[t];
  __syncthreads();

  if (threadIdx.x < 32) {
    int lane = threadIdx.x;
    unsigned kw = 0u;  // keep word for columns [32*lane, 32*lane+32)
#pragma unroll
    for (int jj = 0; jj < 32; jj++) {
      int j = lane * 32 + jj;
      bool v = (j < K_CAND) && (g_cscore[j] > SCORE_THR);
      if (v) kw |= (1u << jj);
    }
    for (int c = 0; c < 32; c++) {
      unsigned bkw = __shfl_sync(0xFFFFFFFFu, kw, c);  // current chunk's keep word
      int base = c * 32;
#pragma unroll
      for (int r = 0; r < 32; r++) {
        int i = base + r;
        if (i < K_CAND) {
          unsigned rowl = ssup[i * 32 + lane];  // conflict-free
          unsigned rowc = ssup[i * 32 + c];     // broadcast
          if (bkw & (1u << r)) {
            kw  &= ~rowl;
            bkw &= ~rowc;
          }
        }
      }
    }
    skeep[lane] = kw;
  }
  __syncthreads();

  int t = threadIdx.x;
  if (t < K_CAND) {
    bool keep = (skeep[t >> 5] >> (t & 31)) & 1u;
    float kf = keep ? 1.0f : 0.0f;
    out[t * 4 + 0] = g_cx1[t] * kf;
    out[t * 4 + 1] = g_cy1[t] * kf;
    out[t * 4 + 2] = g_cx2[t] * kf;
    out[t * 4 + 3] = g_cy2[t] * kf;
    out[4000 + t] = keep ? (float)(g_clabel[t] + 1) : 0.0f;
    out[5000 + t] = g_cscore[t] * kf;
    out[6000 + t] = kf;
  }
}

// ---------------- launch ----------------
extern "C" void kernel_launch(void* const* d_in, const int* in_sizes, int n_in,
                              void* d_out, int out_size) {
  const float* scores = (const float*)d_in[0];
  const float* boxes  = (const float*)d_in[1];
  float* out = (float*)d_out;

  cudaFuncSetAttribute(k_final, cudaFuncAttributeMaxDynamicSharedMemorySize, 128000);

  k_reduce<<<1184, 256>>>(scores);          // 148 SMs x 8 blocks = 1 full wave
  k_mid<<<MID_BLOCKS, MID_THREADS>>>(boxes);
  k_final<<<1, 1024, 128000>>>(out);
}